// round 15
// baseline (speedup 1.0000x reference)
#include <cuda_runtime.h>
#include <math.h>

#define Bv 16
#define Tv 256
#define Hv 512
#define Vv 32
#define NBLK 128
#define NTHR 256

// smem layout (floats)
#define SM_W0C  0                       // ctx cols of W0: 16 slots * 129 f4 = 8256 f
#define SM_W1   8256                    // 16 slots * 257 f4 = 16448 f
#define SM_WQ   24704                   // Wq slice: 32 rows * 129 f4 = 16512 f
#define SM_RED  41216                   // 2 WG * 2048 f (also P5 h1 stage)
#define SM_SG   45312                   // 2 * 128
#define SM_SQ   45568                   // 2 * 512
#define SM_SV   46592                   // 512 (shared)
#define SM_SW   47104                   // 2 * 16 (exp(score) staging)
#define SMEM_FLOATS 47136               // 188544 bytes

__device__ float g_Kproj[Bv*Tv*Hv];
__device__ float g_qp[Bv*Hv];
__device__ float g_ctx[2][Bv*Hv];       // UNNORMALIZED ctx (exp-weighted enc sums)
__device__ float g_den[2][Bv];          // softmax denominators (per parity)
__device__ float g_h[2][2][Bv*Hv];      // [layer][parity][b*H+h]
__device__ unsigned g_cnt2[2*32];       // per-WG-set barrier counter (padded)
__device__ unsigned g_gen2[2*32];       // per-WG-set generation (padded)
__device__ unsigned g_scnt[Bv*8];       // per-batch qp sub-barrier counters (padded)
__device__ unsigned g_sgen[Bv*8];

__device__ __forceinline__ float warp_sum(float v){
#pragma unroll
    for(int o=16;o>0;o>>=1) v += __shfl_xor_sync(0xffffffffu,v,o);
    return v;
}
__device__ __forceinline__ float sigf(float x){ return 1.0f/(1.0f+expf(-x)); }
__device__ __forceinline__ float tanha(float x){ float y; asm("tanh.approx.f32 %0,%1;":"=f"(y):"f"(x)); return y; }
__device__ __forceinline__ unsigned ld_acq(const unsigned* p){
    unsigned v; asm volatile("ld.acquire.gpu.global.u32 %0,[%1];":"=r"(v):"l"(p):"memory"); return v;
}
__device__ __forceinline__ unsigned atom_add_acqrel(unsigned* p, unsigned v){
    unsigned old; asm volatile("atom.acq_rel.gpu.global.add.u32 %0,[%1],%2;":"=r"(old):"l"(p),"r"(v):"memory"); return old;
}
__device__ __forceinline__ void st_rel(unsigned* p, unsigned v){
    asm volatile("st.release.gpu.global.u32 [%0],%1;"::"l"(p),"r"(v):"memory");
}
__device__ __forceinline__ void wg_bar(int wg){
    asm volatile("bar.sync %0,%1;"::"r"(1+wg),"r"(128):"memory");
}
// flat split-phase grid barrier (R10 — best measured)
__device__ __forceinline__ void gb_arrive(unsigned k, int wg, int wg_tid){
    if(wg_tid==0){
        unsigned old = atom_add_acqrel(&g_cnt2[wg*32], 1u);
        if(old == k*(unsigned)NBLK - 1u) st_rel(&g_gen2[wg*32], k);
    }
}
__device__ __forceinline__ void gb_wait(unsigned k, int wg, int wg_tid){
    if(wg_tid==0){
        while(ld_acq(&g_gen2[wg*32]) < k) __nanosleep(32);
    }
    wg_bar(wg);
}

// ---------- Kproj = enc @ Wk^T + bk ----------
__global__ void kproj_kernel(const float* __restrict__ enc, const float* __restrict__ Wk,
                             const float* __restrict__ bk){
    __shared__ float As[16][65], Bs[16][65];
    const int bm = blockIdx.x*64, bn = blockIdx.y*64, tid = threadIdx.x;
    const int tm = (tid/16)*4, tn = (tid%16)*4;
    float acc[4][4] = {};
    for(int k0=0;k0<Hv;k0+=16){
        for(int i=tid;i<64*16;i+=NTHR){
            int m=i>>4,k=i&15;
            As[k][m]=enc[(size_t)(bm+m)*Hv+k0+k];
            Bs[k][m]=Wk [(size_t)(bn+m)*Hv+k0+k];
        }
        __syncthreads();
#pragma unroll
        for(int k=0;k<16;k++){
            float a[4],b[4];
#pragma unroll
            for(int x=0;x<4;x++){ a[x]=As[k][tm+x]; b[x]=Bs[k][tn+x]; }
#pragma unroll
            for(int x=0;x<4;x++)
#pragma unroll
                for(int y=0;y<4;y++) acc[x][y]+=a[x]*b[y];
        }
        __syncthreads();
    }
#pragma unroll
    for(int x=0;x<4;x++)
#pragma unroll
        for(int y=0;y<4;y++)
            g_Kproj[(size_t)(bm+tm+x)*Hv+bn+tn+y]=acc[x][y]+bk[bn+tn+y];
}

// ---------- init ----------
__global__ void decoder_init(const float* __restrict__ h0in,
                             const float* __restrict__ Wq, const float* __restrict__ bq){
    const int tid=threadIdx.x, blk=blockIdx.x, gid=blk*NTHR+tid;
    if(gid<Bv*Hv){
        g_h[0][0][gid]=h0in[gid];
        g_h[1][0][gid]=h0in[Bv*Hv+gid];
        g_ctx[0][gid]=0.f; g_ctx[1][gid]=0.f;
    }
    if(gid<64){ g_cnt2[gid]=0u; g_gen2[gid]=0u; }
    if(gid>=64 && gid<64+Bv*8){ g_scnt[gid-64]=0u; g_sgen[gid-64]=0u; }
    if(gid>=192 && gid<192+2*Bv) ((float*)g_den)[gid-192]=0.f;
    const int ab=blk>>3, sub=blk&7, wid=tid>>5, lane=tid&31;
    const float4* h14=(const float4*)(h0in+Bv*Hv+ab*Hv);
#pragma unroll
    for(int r=0;r<8;r++){
        const int hrow=sub*64+r*8+wid;
        const float4* wr=(const float4*)(Wq+(size_t)hrow*Hv);
        float acc=0.f;
#pragma unroll
        for(int i=0;i<4;i++){
            float4 w4=wr[i*32+lane], x4=h14[i*32+lane];
            acc+=w4.x*x4.x+w4.y*x4.y+w4.z*x4.z+w4.w*x4.w;
        }
        acc=warp_sum(acc);
        if(lane==0) g_qp[ab*Hv+hrow]=acc+bq[hrow];
    }
}

// ---------- persistent decoder ----------
__global__ void __launch_bounds__(NTHR,1)
decoder_main(const float* __restrict__ enc, const float* __restrict__ c0in,
             const float* __restrict__ Wq, const float* __restrict__ bq,
             const float* __restrict__ v,  const float* __restrict__ vb,
             const float* __restrict__ Wih0, const float* __restrict__ bih0,
             const float* __restrict__ Whh0, const float* __restrict__ bhh0,
             const float* __restrict__ Wih1, const float* __restrict__ bih1,
             const float* __restrict__ Whh1, const float* __restrict__ bhh1,
             const float* __restrict__ Wout, const float* __restrict__ bout,
             float* __restrict__ out){
    extern __shared__ float sm[];
    float4* smW0c = (float4*)(sm + SM_W0C);
    float4* smW1  = (float4*)(sm + SM_W1);
    float4* smWq  = (float4*)(sm + SM_WQ);

    const int tid=threadIdx.x, blk=blockIdx.x;
    const int wg = tid>>7, wg_tid = tid&127;
    const int wwid = wg_tid>>5, wlane = wg_tid&31;
    const int sub16 = blk&15, t0 = sub16*16;

    // ---- prologue ----
    // W0 ctx-columns only (x k 512..1023 -> Wih0 f4 cols 128..255)
    for(int idx=tid; idx<16*128; idx+=NTHR){
        const int slot=idx>>7, c=idx&127;
        const int u=slot>>2, g=slot&3;
        const int grow=g*512+blk*4+u;
        smW0c[slot*129+c]=((const float4*)Wih0)[(size_t)grow*256+128+c];
    }
    // W1 full
    for(int idx=tid; idx<16*256; idx+=NTHR){
        const int slot=idx>>8, c=idx&255;
        const int u=slot>>2, g=slot&3;
        const int grow=g*512+blk*4+u;
        float4 val = (c<128)? ((const float4*)Wih1)[(size_t)grow*128+c]
                            : ((const float4*)Whh1)[(size_t)grow*128+(c-128)];
        smW1[slot*257+c]=val;
    }
    // Wq slice: rows sub16*32 .. +32
    for(int idx=tid; idx<32*128; idx+=NTHR){
        const int r=idx>>7, c=idx&127;
        smWq[r*129+c]=((const float4*)Wq)[(size_t)(sub16*32+r)*128+c];
    }
    sm[SM_SV+tid]=v[tid]; sm[SM_SV+tid+256]=v[tid+256];
    const float vb0=vb[0];

    const int ab = wg*8 + (blk>>4);
    const int kc = wg_tid>>3, rg = (wg_tid>>1)&3, bg = wg_tid&1;
    const int r16 = wg_tid>>3;
    const int growB=(r16>>2)*512+blk*4+(r16&3);
    const float bs0=bih0[growB]+bhh0[growB];
    const float bs1=bih1[growB]+bhh1[growB];
    const int ulc=wg_tid>>3, b8c=wg_tid&7, bglobc=wg*8+b8c, unitc=blk*4+ulc;
    float c0r=0.f, c1r=0.f;
    if(wg_tid<32){
        c0r=c0in[bglobc*Hv+unitc];
        c1r=c0in[Bv*Hv+bglobc*Hv+unitc];
    }
    float* redw = sm + SM_RED + wg*2048;
    float* sgw  = sm + SM_SG  + wg*128;
    float* sqw  = sm + SM_SQ  + wg*512;
    float* sww  = sm + SM_SW  + wg*16;
    __syncthreads();

    unsigned bar_k=1, sub_k=1;

    for(int s=0;s<Tv;s++){
        const int p=s&1, pn=p^1;

        // ======== P1+P2 fused: local scores -> exp -> unnormalized ctx + den ========
        ((float4*)sqw)[wg_tid] = ((const float4*)(g_qp+ab*Hv))[wg_tid];
        if(wg_tid==0) g_den[pn][ab]=0.f;
        if(wg_tid<32) g_ctx[pn][wg*4096 + blk*32 + wg_tid]=0.f;
        wg_bar(wg);
        {
            const float4* sq4=(const float4*)sqw;
            const float4* sv4=(const float4*)(sm+SM_SV);
            const float4* kp[4];
#pragma unroll
            for(int r=0;r<4;r++)
                kp[r]=(const float4*)(g_Kproj+(size_t)(ab*Tv+t0+wwid*4+r)*Hv);
            float acc[4]={};
#pragma unroll
            for(int i=0;i<4;i++){
                float4 q4=sq4[i*32+wlane], vv=sv4[i*32+wlane];
#pragma unroll
                for(int r=0;r<4;r++){
                    float4 k4=kp[r][i*32+wlane];
                    acc[r]+=vv.x*tanha(q4.x+k4.x)+vv.y*tanha(q4.y+k4.y)
                          +vv.z*tanha(q4.z+k4.z)+vv.w*tanha(q4.w+k4.w);
                }
            }
#pragma unroll
            for(int r=0;r<4;r++){
                float sres=warp_sum(acc[r]);
                if(wlane==0) sww[wwid*4+r]=__expf(sres+vb0);
            }
        }
        wg_bar(wg);
        if(wg_tid==0){
            float d=0.f;
#pragma unroll
            for(int j=0;j<16;j++) d+=sww[j];
            atomicAdd(&g_den[p][ab], d);
        }
        {
            const int h4=wg_tid*4;
            float a0=0.f,a1=0.f,a2=0.f,a3=0.f;
#pragma unroll 4
            for(int j=0;j<16;j++){
                const float wj=sww[j];
                const float4 e4=*(const float4*)(enc+(size_t)(ab*Tv+t0+j)*Hv+h4);
                a0+=wj*e4.x; a1+=wj*e4.y; a2+=wj*e4.z; a3+=wj*e4.w;
            }
            float* cdst=&g_ctx[p][ab*Hv+h4];
            atomicAdd(cdst,a0); atomicAdd(cdst+1,a1);
            atomicAdd(cdst+2,a2); atomicAdd(cdst+3,a3);
        }

        // ======== barrier A (split-phase) + P3 ========
        wg_bar(wg);
        gb_arrive(bar_k, wg, wg_tid);
        float acc[4][4]={};
        // --- P3a: enc (kc<8) or h0_old (kc>=8) parts; weights streamed from L2 (covered) ---
        if(kc<8){
            const float4* ep[4];
#pragma unroll
            for(int j=0;j<4;j++)
                ep[j]=(const float4*)(enc+((size_t)((wg*8+bg*4+j)*Tv+s))*Hv);
            const float4* wg0=(const float4*)Wih0;
#pragma unroll 8
            for(int k4=0;k4<16;k4++){
                const int kgw=kc*16+k4;
                float4 xv[4], wv[4];
#pragma unroll
                for(int j=0;j<4;j++) xv[j]=ep[j][kgw];
#pragma unroll
                for(int i=0;i<4;i++) wv[i]=wg0[(size_t)(rg*512+blk*4+i)*256+kgw];
#pragma unroll
                for(int i=0;i<4;i++)
#pragma unroll
                    for(int j=0;j<4;j++)
                        acc[i][j]+=wv[i].x*xv[j].x+wv[i].y*xv[j].y+wv[i].z*xv[j].z+wv[i].w*xv[j].w;
            }
        }else{
            const float4* hp=(const float4*)g_h[0][p];
            const float4* wh0=(const float4*)Whh0;
#pragma unroll 8
            for(int k4=0;k4<16;k4++){
                const int kk=(kc-8)*16+k4;
                float4 xv[4], wv[4];
#pragma unroll
                for(int j=0;j<4;j++) xv[j]=hp[(wg*8+bg*4+j)*128+kk];
#pragma unroll
                for(int i=0;i<4;i++) wv[i]=wh0[(size_t)(rg*512+blk*4+i)*128+kk];
#pragma unroll
                for(int i=0;i<4;i++)
#pragma unroll
                    for(int j=0;j<4;j++)
                        acc[i][j]+=wv[i].x*xv[j].x+wv[i].y*xv[j].y+wv[i].z*xv[j].z+wv[i].w*xv[j].w;
            }
        }
        gb_wait(bar_k, wg, wg_tid); bar_k++;
        // --- P3b: ctx part (smem weights) + deferred 1/den scaling ---
        {
            float rden[4];
            {
                const float4 dv = *reinterpret_cast<const float4*>(&g_den[p][wg*8+bg*4]);
                rden[0]=1.0f/dv.x; rden[1]=1.0f/dv.y; rden[2]=1.0f/dv.z; rden[3]=1.0f/dv.w;
            }
            const float4* cp=(const float4*)g_ctx[p];
            float accc[4][4]={};
#pragma unroll 8
            for(int k4=0;k4<8;k4++){
                const int kk=kc*8+k4;
                float4 xv[4], wv[4];
#pragma unroll
                for(int j=0;j<4;j++) xv[j]=cp[(wg*8+bg*4+j)*128+kk];
#pragma unroll
                for(int i=0;i<4;i++) wv[i]=smW0c[(i*4+rg)*129+kk];
#pragma unroll
                for(int i=0;i<4;i++)
#pragma unroll
                    for(int j=0;j<4;j++)
                        accc[i][j]+=wv[i].x*xv[j].x+wv[i].y*xv[j].y+wv[i].z*xv[j].z+wv[i].w*xv[j].w;
            }
            float* red = redw+kc*128;
#pragma unroll
            for(int i=0;i<4;i++)
                *(float4*)(red+(rg*4+i)*8+bg*4)=make_float4(acc[i][0]+accc[i][0]*rden[0],
                                                            acc[i][1]+accc[i][1]*rden[1],
                                                            acc[i][2]+accc[i][2]*rden[2],
                                                            acc[i][3]+accc[i][3]*rden[3]);
        }
        wg_bar(wg);
        {
            float g=0.f;
#pragma unroll
            for(int kk=0;kk<16;kk++) g+=redw[kk*128+wg_tid];
            sgw[wg_tid]=g+bs0;
        }
        wg_bar(wg);
        if(wg_tid<32){
            const float gi=sgw[(0+ulc)*8+b8c], gf=sgw[(4+ulc)*8+b8c];
            const float gg=sgw[(8+ulc)*8+b8c], go=sgw[(12+ulc)*8+b8c];
            c0r=sigf(gf)*c0r+sigf(gi)*tanhf(gg);
            g_h[0][pn][bglobc*Hv+unitc]=sigf(go)*tanhf(c0r);
        }

        // ======== barrier B (split-phase) + P4 ========
        wg_bar(wg);
        gb_arrive(bar_k, wg, wg_tid);
        float acc4[4][4]={};
        // --- P4a: h1_old part, 8 k4 ---
        {
            const float4* h1o=(const float4*)g_h[1][p];
#pragma unroll 8
            for(int k4=0;k4<8;k4++){
                const int kk=kc*8+k4;
                float4 xv[4], wv[4];
#pragma unroll
                for(int j=0;j<4;j++) xv[j]=h1o[(wg*8+bg*4+j)*128+kk];
#pragma unroll
                for(int i=0;i<4;i++) wv[i]=smW1[(i*4+rg)*257+128+kk];
#pragma unroll
                for(int i=0;i<4;i++)
#pragma unroll
                    for(int j=0;j<4;j++)
                        acc4[i][j]+=wv[i].x*xv[j].x+wv[i].y*xv[j].y+wv[i].z*xv[j].z+wv[i].w*xv[j].w;
            }
        }
        gb_wait(bar_k, wg, wg_tid); bar_k++;
        // --- P4b: h0_new part, 8 k4 ---
        {
            const float4* h0n=(const float4*)g_h[0][pn];
#pragma unroll 8
            for(int k4=0;k4<8;k4++){
                const int kk=kc*8+k4;
                float4 xv[4], wv[4];
#pragma unroll
                for(int j=0;j<4;j++) xv[j]=h0n[(wg*8+bg*4+j)*128+kk];
#pragma unroll
                for(int i=0;i<4;i++) wv[i]=smW1[(i*4+rg)*257+kk];
#pragma unroll
                for(int i=0;i<4;i++)
#pragma unroll
                    for(int j=0;j<4;j++)
                        acc4[i][j]+=wv[i].x*xv[j].x+wv[i].y*xv[j].y+wv[i].z*xv[j].z+wv[i].w*xv[j].w;
            }
            float* red = redw+kc*128;
#pragma unroll
            for(int i=0;i<4;i++)
                *(float4*)(red+(rg*4+i)*8+bg*4)=make_float4(acc4[i][0],acc4[i][1],acc4[i][2],acc4[i][3]);
        }
        wg_bar(wg);
        {
            float g=0.f;
#pragma unroll
            for(int kk=0;kk<16;kk++) g+=redw[kk*128+wg_tid];
            sgw[wg_tid]=g+bs1;
        }
        wg_bar(wg);
        if(wg_tid<32){
            const float gi=sgw[(0+ulc)*8+b8c], gf=sgw[(4+ulc)*8+b8c];
            const float gg=sgw[(8+ulc)*8+b8c], go=sgw[(12+ulc)*8+b8c];
            c1r=sigf(gf)*c1r+sigf(gi)*tanhf(gg);
            g_h[1][pn][bglobc*Hv+unitc]=sigf(go)*tanhf(c1r);
        }

        // ======== barrier C ========
        wg_bar(wg);
        gb_arrive(bar_k, wg, wg_tid);
        gb_wait(bar_k, wg, wg_tid); bar_k++;

        // ======== P5: qp (smem Wq GEMV) ; logits hidden under sub16 wait ========
        {
            float4* st4=(float4*)redw;
            st4[wg_tid]=((const float4*)g_h[1][pn])[ab*128+wg_tid];
            wg_bar(wg);
#pragma unroll
            for(int jj=0;jj<2;jj++){
                float accq[4]={};
#pragma unroll
                for(int i=0;i<4;i++){
                    float4 x4=st4[i*32+wlane];
#pragma unroll
                    for(int r=0;r<4;r++){
                        float4 w4=smWq[(wwid*8+jj*4+r)*129 + i*32+wlane];
                        accq[r]+=w4.x*x4.x+w4.y*x4.y+w4.z*x4.z+w4.w*x4.w;
                    }
                }
#pragma unroll
                for(int r=0;r<4;r++){
                    float sres=warp_sum(accq[r]);
                    const int h=sub16*32+wwid*8+jj*4+r;
                    if(wlane==0) g_qp[ab*Hv+h]=sres+bq[h];
                }
            }
            // split-phase sub16: arrive, do logits (off-recurrence) under the wait
            wg_bar(wg);
            if(wg_tid==0){
                unsigned old=atom_add_acqrel(&g_scnt[ab*8],1u);
                if(old==sub_k*16u-1u) st_rel(&g_sgen[ab*8],sub_k);
            }
            if(wwid<2){
                const int vo=sub16*2+wwid;
                const float4* wo4=(const float4*)(Wout+(size_t)vo*Hv);
                float acco=0.f;
#pragma unroll
                for(int i=0;i<4;i++){
                    float4 w4=wo4[i*32+wlane], x4=st4[i*32+wlane];
                    acco+=w4.x*x4.x+w4.y*x4.y+w4.z*x4.z+w4.w*x4.w;
                }
                acco=warp_sum(acco);
                if(wlane==0) out[(size_t)(ab*Tv+s)*Vv+vo]=acco+bout[vo];
            }
            if(wg_tid==0){
                while(ld_acq(&g_sgen[ab*8])<sub_k) __nanosleep(32);
            }
            wg_bar(wg);
            sub_k++;
        }
    }
}

extern "C" void kernel_launch(void* const* d_in, const int* in_sizes, int n_in,
                              void* d_out, int out_size){
    const float* enc  =(const float*)d_in[0];
    const float* h0in =(const float*)d_in[1];
    const float* c0in =(const float*)d_in[2];
    const float* Wq   =(const float*)d_in[4];
    const float* bq   =(const float*)d_in[5];
    const float* Wk   =(const float*)d_in[6];
    const float* bk   =(const float*)d_in[7];
    const float* v    =(const float*)d_in[8];
    const float* vb   =(const float*)d_in[9];
    const float* Wih0 =(const float*)d_in[10];
    const float* bih0 =(const float*)d_in[11];
    const float* Whh0 =(const float*)d_in[12];
    const float* bhh0 =(const float*)d_in[13];
    const float* Wih1 =(const float*)d_in[14];
    const float* bih1 =(const float*)d_in[15];
    const float* Whh1 =(const float*)d_in[16];
    const float* bhh1 =(const float*)d_in[17];
    const float* Wout =(const float*)d_in[18];
    const float* bout =(const float*)d_in[19];
    float* out=(float*)d_out;

    const int smem_bytes = SMEM_FLOATS*4;
    cudaFuncSetAttribute(decoder_main, cudaFuncAttributeMaxDynamicSharedMemorySize, smem_bytes);

    kproj_kernel<<<dim3(64,8),NTHR>>>(enc,Wk,bk);
    decoder_init<<<NBLK,NTHR>>>(h0in,Wq,bq);
    decoder_main<<<NBLK,NTHR,smem_bytes>>>(enc,c0in,Wq,bq,v,vb,
        Wih0,bih0,Whh0,bhh0,Wih1,bih1,Whh1,bhh1,Wout,bout,out);
}

// round 17
// speedup vs baseline: 1.1407x; 1.1407x over previous
#include <cuda_runtime.h>
#include <math.h>

#define Bv 16
#define Tv 256
#define Hv 512
#define Vv 32
#define NBLK 128
#define NTHR 256

// smem layout (floats)
#define SM_W0   0                       // 16 slots * 385 float4 = 24640 f
#define SM_W1   24640                   // 16 slots * 257 f4 = 16448 f
#define SM_RED  41088                   // 2 WG * 2048 f (also P5 h1 stage)
#define SM_SG   45184                   // 2 * 128
#define SM_SQ   45440                   // 2 * 512
#define SM_SV   46464                   // 512 (shared)
#define SM_SW   46976                   // 2 * 16 (exp(score) staging)
#define SMEM_FLOATS 47008               // 188032 bytes

__device__ float g_Kproj[Bv*Tv*Hv];
__device__ float g_qp[Bv*Hv];
__device__ float g_ctx[2][Bv*Hv];       // UNNORMALIZED ctx (exp-weighted enc sums)
__device__ float g_den[2][Bv];          // softmax denominators (per parity)
__device__ float g_h[2][2][Bv*Hv];      // [layer][parity][b*H+h]
__device__ unsigned g_cnt2[2*32];       // per-WG-set barrier counter (padded)
__device__ unsigned g_gen2[2*32];       // per-WG-set generation (padded)
__device__ unsigned g_scnt[Bv*8];       // per-batch qp sub-barrier counters (padded)
__device__ unsigned g_sgen[Bv*8];

__device__ __forceinline__ float warp_sum(float v){
#pragma unroll
    for(int o=16;o>0;o>>=1) v += __shfl_xor_sync(0xffffffffu,v,o);
    return v;
}
__device__ __forceinline__ float sigf(float x){ return 1.0f/(1.0f+expf(-x)); }
__device__ __forceinline__ float tanha(float x){ float y; asm("tanh.approx.f32 %0,%1;":"=f"(y):"f"(x)); return y; }
__device__ __forceinline__ unsigned ld_acq(const unsigned* p){
    unsigned v; asm volatile("ld.acquire.gpu.global.u32 %0,[%1];":"=r"(v):"l"(p):"memory"); return v;
}
__device__ __forceinline__ unsigned atom_add_acqrel(unsigned* p, unsigned v){
    unsigned old; asm volatile("atom.acq_rel.gpu.global.add.u32 %0,[%1],%2;":"=r"(old):"l"(p),"r"(v):"memory"); return old;
}
__device__ __forceinline__ void st_rel(unsigned* p, unsigned v){
    asm volatile("st.release.gpu.global.u32 [%0],%1;"::"l"(p),"r"(v):"memory");
}
__device__ __forceinline__ void wg_bar(int wg){
    asm volatile("bar.sync %0,%1;"::"r"(1+wg),"r"(128):"memory");
}
// flat split-phase grid barrier (R10 — best measured)
__device__ __forceinline__ void gb_arrive(unsigned k, int wg, int wg_tid){
    if(wg_tid==0){
        unsigned old = atom_add_acqrel(&g_cnt2[wg*32], 1u);
        if(old == k*(unsigned)NBLK - 1u) st_rel(&g_gen2[wg*32], k);
    }
}
__device__ __forceinline__ void gb_wait(unsigned k, int wg, int wg_tid){
    if(wg_tid==0){
        while(ld_acq(&g_gen2[wg*32]) < k) __nanosleep(32);
    }
    wg_bar(wg);
}

// ---------- Kproj = enc @ Wk^T + bk ----------
__global__ void kproj_kernel(const float* __restrict__ enc, const float* __restrict__ Wk,
                             const float* __restrict__ bk){
    __shared__ float As[16][65], Bs[16][65];
    const int bm = blockIdx.x*64, bn = blockIdx.y*64, tid = threadIdx.x;
    const int tm = (tid/16)*4, tn = (tid%16)*4;
    float acc[4][4] = {};
    for(int k0=0;k0<Hv;k0+=16){
        for(int i=tid;i<64*16;i+=NTHR){
            int m=i>>4,k=i&15;
            As[k][m]=enc[(size_t)(bm+m)*Hv+k0+k];
            Bs[k][m]=Wk [(size_t)(bn+m)*Hv+k0+k];
        }
        __syncthreads();
#pragma unroll
        for(int k=0;k<16;k++){
            float a[4],b[4];
#pragma unroll
            for(int x=0;x<4;x++){ a[x]=As[k][tm+x]; b[x]=Bs[k][tn+x]; }
#pragma unroll
            for(int x=0;x<4;x++)
#pragma unroll
                for(int y=0;y<4;y++) acc[x][y]+=a[x]*b[y];
        }
        __syncthreads();
    }
#pragma unroll
    for(int x=0;x<4;x++)
#pragma unroll
        for(int y=0;y<4;y++)
            g_Kproj[(size_t)(bm+tm+x)*Hv+bn+tn+y]=acc[x][y]+bk[bn+tn+y];
}

// ---------- init ----------
__global__ void decoder_init(const float* __restrict__ h0in,
                             const float* __restrict__ Wq, const float* __restrict__ bq){
    const int tid=threadIdx.x, blk=blockIdx.x, gid=blk*NTHR+tid;
    if(gid<Bv*Hv){
        g_h[0][0][gid]=h0in[gid];
        g_h[1][0][gid]=h0in[Bv*Hv+gid];
        g_ctx[0][gid]=0.f; g_ctx[1][gid]=0.f;
    }
    if(gid<64){ g_cnt2[gid]=0u; g_gen2[gid]=0u; }
    if(gid>=64 && gid<64+Bv*8){ g_scnt[gid-64]=0u; g_sgen[gid-64]=0u; }
    if(gid>=192 && gid<192+2*Bv) ((float*)g_den)[gid-192]=0.f;
    const int ab=blk>>3, sub=blk&7, wid=tid>>5, lane=tid&31;
    const float4* h14=(const float4*)(h0in+Bv*Hv+ab*Hv);
#pragma unroll
    for(int r=0;r<8;r++){
        const int hrow=sub*64+r*8+wid;
        const float4* wr=(const float4*)(Wq+(size_t)hrow*Hv);
        float acc=0.f;
#pragma unroll
        for(int i=0;i<4;i++){
            float4 w4=wr[i*32+lane], x4=h14[i*32+lane];
            acc+=w4.x*x4.x+w4.y*x4.y+w4.z*x4.z+w4.w*x4.w;
        }
        acc=warp_sum(acc);
        if(lane==0) g_qp[ab*Hv+hrow]=acc+bq[hrow];
    }
}

// ---------- persistent decoder ----------
__global__ void __launch_bounds__(NTHR,1)
decoder_main(const float* __restrict__ enc, const float* __restrict__ c0in,
             const float* __restrict__ Wq, const float* __restrict__ bq,
             const float* __restrict__ v,  const float* __restrict__ vb,
             const float* __restrict__ Wih0, const float* __restrict__ bih0,
             const float* __restrict__ Whh0, const float* __restrict__ bhh0,
             const float* __restrict__ Wih1, const float* __restrict__ bih1,
             const float* __restrict__ Whh1, const float* __restrict__ bhh1,
             const float* __restrict__ Wout, const float* __restrict__ bout,
             float* __restrict__ out){
    extern __shared__ float sm[];
    float4* smW0 = (float4*)(sm + SM_W0);
    float4* smW1 = (float4*)(sm + SM_W1);

    const int tid=threadIdx.x, blk=blockIdx.x;
    const int wg = tid>>7, wg_tid = tid&127;
    const int wwid = wg_tid>>5, wlane = wg_tid&31;
    const int sub16 = blk&15, t0 = sub16*16;

    // ---- prologue ----
    for(int idx=tid; idx<16*384; idx+=NTHR){
        const int slot=idx/384, c=idx-slot*384;
        const int u=slot>>2, g=slot&3;
        const int grow=g*512+blk*4+u;
        float4 val = (c<256)? ((const float4*)Wih0)[(size_t)grow*256+c]
                            : ((const float4*)Whh0)[(size_t)grow*128+(c-256)];
        smW0[slot*385+c]=val;
    }
    for(int idx=tid; idx<16*256; idx+=NTHR){
        const int slot=idx>>8, c=idx&255;
        const int u=slot>>2, g=slot&3;
        const int grow=g*512+blk*4+u;
        float4 val = (c<128)? ((const float4*)Wih1)[(size_t)grow*128+c]
                            : ((const float4*)Whh1)[(size_t)grow*128+(c-128)];
        smW1[slot*257+c]=val;
    }
    sm[SM_SV+tid]=v[tid]; sm[SM_SV+tid+256]=v[tid+256];
    const float vb0=vb[0];

    const int ab = wg*8 + (blk>>4);
    const int kc = wg_tid>>3, rg = (wg_tid>>1)&3, bg = wg_tid&1;
    const int r16 = wg_tid>>3;
    const int growB=(r16>>2)*512+blk*4+(r16&3);
    const float bs0=bih0[growB]+bhh0[growB];
    const float bs1=bih1[growB]+bhh1[growB];
    const int ulc=wg_tid>>3, b8c=wg_tid&7, bglobc=wg*8+b8c, unitc=blk*4+ulc;
    float c0r=0.f, c1r=0.f;
    if(wg_tid<32){
        c0r=c0in[bglobc*Hv+unitc];
        c1r=c0in[Bv*Hv+bglobc*Hv+unitc];
    }
    float* redw = sm + SM_RED + wg*2048;
    float* sgw  = sm + SM_SG  + wg*128;
    float* sqw  = sm + SM_SQ  + wg*512;
    float* sww  = sm + SM_SW  + wg*16;
    __syncthreads();

    unsigned bar_k=1, sub_k=1;

    for(int s=0;s<Tv;s++){
        const int p=s&1, pn=p^1;

        // ======== P1+P2 fused: local scores -> exp -> unnormalized ctx + den ========
        ((float4*)sqw)[wg_tid] = ((const float4*)(g_qp+ab*Hv))[wg_tid];
        if(wg_tid==0) g_den[pn][ab]=0.f;
        if(wg_tid<32) g_ctx[pn][wg*4096 + blk*32 + wg_tid]=0.f;
        wg_bar(wg);
        {
            const float4* sq4=(const float4*)sqw;
            const float4* sv4=(const float4*)(sm+SM_SV);
            const float4* kp[4];
#pragma unroll
            for(int r=0;r<4;r++)
                kp[r]=(const float4*)(g_Kproj+(size_t)(ab*Tv+t0+wwid*4+r)*Hv);
            float acc[4]={};
#pragma unroll
            for(int i=0;i<4;i++){
                float4 q4=sq4[i*32+wlane], vv=sv4[i*32+wlane];
#pragma unroll
                for(int r=0;r<4;r++){
                    float4 k4=kp[r][i*32+wlane];
                    acc[r]+=vv.x*tanha(q4.x+k4.x)+vv.y*tanha(q4.y+k4.y)
                          +vv.z*tanha(q4.z+k4.z)+vv.w*tanha(q4.w+k4.w);
                }
            }
#pragma unroll
            for(int r=0;r<4;r++){
                float sres=warp_sum(acc[r]);
                if(wlane==0) sww[wwid*4+r]=__expf(sres+vb0);
            }
        }
        wg_bar(wg);
        if(wg_tid==0){
            float d=0.f;
#pragma unroll
            for(int j=0;j<16;j++) d+=sww[j];
            atomicAdd(&g_den[p][ab], d);
        }
        {
            const int h4=wg_tid*4;
            float a0=0.f,a1=0.f,a2=0.f,a3=0.f;
#pragma unroll 4
            for(int j=0;j<16;j++){
                const float wj=sww[j];
                const float4 e4=*(const float4*)(enc+(size_t)(ab*Tv+t0+j)*Hv+h4);
                a0+=wj*e4.x; a1+=wj*e4.y; a2+=wj*e4.z; a3+=wj*e4.w;
            }
            float* cdst=&g_ctx[p][ab*Hv+h4];
            atomicAdd(cdst,a0); atomicAdd(cdst+1,a1);
            atomicAdd(cdst+2,a2); atomicAdd(cdst+3,a3);
        }

        // ======== barrier A (split-phase) + P3 ========
        wg_bar(wg);
        gb_arrive(bar_k, wg, wg_tid);
        float acc[4][4]={};
        // --- P3a: enc (kc<8) or h0_old (kc>=8) part, 16 k4 each (smem weights) ---
        if(kc<8){
            const float4* ep[4];
#pragma unroll
            for(int j=0;j<4;j++)
                ep[j]=(const float4*)(enc+((size_t)((wg*8+bg*4+j)*Tv+s))*Hv);
#pragma unroll 8
            for(int k4=0;k4<16;k4++){
                const int kgw=kc*16+k4;
                float4 xv[4], wv[4];
#pragma unroll
                for(int j=0;j<4;j++) xv[j]=ep[j][kgw];
#pragma unroll
                for(int i=0;i<4;i++) wv[i]=smW0[(i*4+rg)*385+kgw];
#pragma unroll
                for(int i=0;i<4;i++)
#pragma unroll
                    for(int j=0;j<4;j++)
                        acc[i][j]+=wv[i].x*xv[j].x+wv[i].y*xv[j].y+wv[i].z*xv[j].z+wv[i].w*xv[j].w;
            }
        }else{
            const float4* hp=(const float4*)g_h[0][p];
#pragma unroll 8
            for(int k4=0;k4<16;k4++){
                const int kk=(kc-8)*16+k4;
                float4 xv[4], wv[4];
#pragma unroll
                for(int j=0;j<4;j++) xv[j]=hp[(wg*8+bg*4+j)*128+kk];
#pragma unroll
                for(int i=0;i<4;i++) wv[i]=smW0[(i*4+rg)*385+256+kk];
#pragma unroll
                for(int i=0;i<4;i++)
#pragma unroll
                    for(int j=0;j<4;j++)
                        acc[i][j]+=wv[i].x*xv[j].x+wv[i].y*xv[j].y+wv[i].z*xv[j].z+wv[i].w*xv[j].w;
            }
        }
        gb_wait(bar_k, wg, wg_tid); bar_k++;
        // --- P3b: ctx part (unnormalized) + deferred 1/den scaling ---
        {
            float rden[4];
            {
                const float4 dv = *reinterpret_cast<const float4*>(&g_den[p][wg*8+bg*4]);
                rden[0]=1.0f/dv.x; rden[1]=1.0f/dv.y; rden[2]=1.0f/dv.z; rden[3]=1.0f/dv.w;
            }
            const float4* cp=(const float4*)g_ctx[p];
            float accc[4][4]={};
#pragma unroll 8
            for(int k4=0;k4<8;k4++){
                const int kk=kc*8+k4;
                float4 xv[4], wv[4];
#pragma unroll
                for(int j=0;j<4;j++) xv[j]=cp[(wg*8+bg*4+j)*128+kk];
#pragma unroll
                for(int i=0;i<4;i++) wv[i]=smW0[(i*4+rg)*385+128+kk];
#pragma unroll
                for(int i=0;i<4;i++)
#pragma unroll
                    for(int j=0;j<4;j++)
                        accc[i][j]+=wv[i].x*xv[j].x+wv[i].y*xv[j].y+wv[i].z*xv[j].z+wv[i].w*xv[j].w;
            }
            float* red = redw+kc*128;
#pragma unroll
            for(int i=0;i<4;i++)
                *(float4*)(red+(rg*4+i)*8+bg*4)=make_float4(acc[i][0]+accc[i][0]*rden[0],
                                                            acc[i][1]+accc[i][1]*rden[1],
                                                            acc[i][2]+accc[i][2]*rden[2],
                                                            acc[i][3]+accc[i][3]*rden[3]);
        }
        wg_bar(wg);
        {
            float g=0.f;
#pragma unroll
            for(int kk=0;kk<16;kk++) g+=redw[kk*128+wg_tid];
            sgw[wg_tid]=g+bs0;
        }
        wg_bar(wg);
        if(wg_tid<32){
            const float gi=sgw[(0+ulc)*8+b8c], gf=sgw[(4+ulc)*8+b8c];
            const float gg=sgw[(8+ulc)*8+b8c], go=sgw[(12+ulc)*8+b8c];
            c0r=sigf(gf)*c0r+sigf(gi)*tanhf(gg);
            g_h[0][pn][bglobc*Hv+unitc]=sigf(go)*tanhf(c0r);
        }

        // ======== barrier B (split-phase) + P4 ========
        wg_bar(wg);
        gb_arrive(bar_k, wg, wg_tid);
        float acc4[4][4]={};
        // --- P4a: h1_old part, 8 k4 ---
        {
            const float4* h1o=(const float4*)g_h[1][p];
#pragma unroll 8
            for(int k4=0;k4<8;k4++){
                const int kk=kc*8+k4;
                float4 xv[4], wv[4];
#pragma unroll
                for(int j=0;j<4;j++) xv[j]=h1o[(wg*8+bg*4+j)*128+kk];
#pragma unroll
                for(int i=0;i<4;i++) wv[i]=smW1[(i*4+rg)*257+128+kk];
#pragma unroll
                for(int i=0;i<4;i++)
#pragma unroll
                    for(int j=0;j<4;j++)
                        acc4[i][j]+=wv[i].x*xv[j].x+wv[i].y*xv[j].y+wv[i].z*xv[j].z+wv[i].w*xv[j].w;
            }
        }
        gb_wait(bar_k, wg, wg_tid); bar_k++;
        // --- P4b: h0_new part, 8 k4 ---
        {
            const float4* h0n=(const float4*)g_h[0][pn];
#pragma unroll 8
            for(int k4=0;k4<8;k4++){
                const int kk=kc*8+k4;
                float4 xv[4], wv[4];
#pragma unroll
                for(int j=0;j<4;j++) xv[j]=h0n[(wg*8+bg*4+j)*128+kk];
#pragma unroll
                for(int i=0;i<4;i++) wv[i]=smW1[(i*4+rg)*257+kk];
#pragma unroll
                for(int i=0;i<4;i++)
#pragma unroll
                    for(int j=0;j<4;j++)
                        acc4[i][j]+=wv[i].x*xv[j].x+wv[i].y*xv[j].y+wv[i].z*xv[j].z+wv[i].w*xv[j].w;
            }
            float* red = redw+kc*128;
#pragma unroll
            for(int i=0;i<4;i++)
                *(float4*)(red+(rg*4+i)*8+bg*4)=make_float4(acc4[i][0],acc4[i][1],acc4[i][2],acc4[i][3]);
        }
        wg_bar(wg);
        {
            float g=0.f;
#pragma unroll
            for(int kk=0;kk<16;kk++) g+=redw[kk*128+wg_tid];
            sgw[wg_tid]=g+bs1;
        }
        wg_bar(wg);
        if(wg_tid<32){
            const float gi=sgw[(0+ulc)*8+b8c], gf=sgw[(4+ulc)*8+b8c];
            const float gg=sgw[(8+ulc)*8+b8c], go=sgw[(12+ulc)*8+b8c];
            c1r=sigf(gf)*c1r+sigf(gi)*tanhf(gg);
            g_h[1][pn][bglobc*Hv+unitc]=sigf(go)*tanhf(c1r);
        }

        // ======== barrier C ========
        wg_bar(wg);
        gb_arrive(bar_k, wg, wg_tid);
        gb_wait(bar_k, wg, wg_tid); bar_k++;

        // ======== P5: qp (next step) ; logits hidden under sub16 wait ========
        {
            float4* st4=(float4*)redw;
            st4[wg_tid]=((const float4*)g_h[1][pn])[ab*128+wg_tid];
            wg_bar(wg);
#pragma unroll
            for(int jj=0;jj<2;jj++){
                float accq[4]={};
#pragma unroll
                for(int i=0;i<4;i++){
                    float4 x4=st4[i*32+wlane];
#pragma unroll
                    for(int r=0;r<4;r++){
                        const int h=sub16*32+wwid*8+jj*4+r;
                        float4 w4=((const float4*)(Wq+(size_t)h*Hv))[i*32+wlane];
                        accq[r]+=w4.x*x4.x+w4.y*x4.y+w4.z*x4.z+w4.w*x4.w;
                    }
                }
#pragma unroll
                for(int r=0;r<4;r++){
                    float sres=warp_sum(accq[r]);
                    const int h=sub16*32+wwid*8+jj*4+r;
                    if(wlane==0) g_qp[ab*Hv+h]=sres+bq[h];
                }
            }
            // split-phase sub16: arrive, compute logits (off-recurrence) under the wait
            wg_bar(wg);
            if(wg_tid==0){
                unsigned old=atom_add_acqrel(&g_scnt[ab*8],1u);
                if(old==sub_k*16u-1u) st_rel(&g_sgen[ab*8],sub_k);
            }
            if(wwid<2){
                const int vo=sub16*2+wwid;
                const float4* wo4=(const float4*)(Wout+(size_t)vo*Hv);
                float acco=0.f;
#pragma unroll
                for(int i=0;i<4;i++){
                    float4 w4=wo4[i*32+wlane], x4=st4[i*32+wlane];
                    acco+=w4.x*x4.x+w4.y*x4.y+w4.z*x4.z+w4.w*x4.w;
                }
                acco=warp_sum(acco);
                if(wlane==0) out[(size_t)(ab*Tv+s)*Vv+vo]=acco+bout[vo];
            }
            if(wg_tid==0){
                while(ld_acq(&g_sgen[ab*8])<sub_k) __nanosleep(32);
            }
            wg_bar(wg);
            sub_k++;
        }
    }
}

extern "C" void kernel_launch(void* const* d_in, const int* in_sizes, int n_in,
                              void* d_out, int out_size){
    const float* enc  =(const float*)d_in[0];
    const float* h0in =(const float*)d_in[1];
    const float* c0in =(const float*)d_in[2];
    const float* Wq   =(const float*)d_in[4];
    const float* bq   =(const float*)d_in[5];
    const float* Wk   =(const float*)d_in[6];
    const float* bk   =(const float*)d_in[7];
    const float* v    =(const float*)d_in[8];
    const float* vb   =(const float*)d_in[9];
    const float* Wih0 =(const float*)d_in[10];
    const float* bih0 =(const float*)d_in[11];
    const float* Whh0 =(const float*)d_in[12];
    const float* bhh0 =(const float*)d_in[13];
    const float* Wih1 =(const float*)d_in[14];
    const float* bih1 =(const float*)d_in[15];
    const float* Whh1 =(const float*)d_in[16];
    const float* bhh1 =(const float*)d_in[17];
    const float* Wout =(const float*)d_in[18];
    const float* bout =(const float*)d_in[19];
    float* out=(float*)d_out;

    const int smem_bytes = SMEM_FLOATS*4;
    cudaFuncSetAttribute(decoder_main, cudaFuncAttributeMaxDynamicSharedMemorySize, smem_bytes);

    kproj_kernel<<<dim3(64,8),NTHR>>>(enc,Wk,bk);
    decoder_init<<<NBLK,NTHR>>>(h0in,Wq,bq);
    decoder_main<<<NBLK,NTHR,smem_bytes>>>(enc,c0in,Wq,bq,v,vb,
        Wih0,bih0,Whh0,bhh0,Wih1,bih1,Whh1,bhh1,Wout,bout,out);
}